// round 7
// baseline (speedup 1.0000x reference)
#include <cuda_runtime.h>
#include <cuda_bf16.h>

// AnisotropicDistance:
// out[b,i,j] = alpha_i * max(||p_i-p_j||^2 + along^2*(||t_i||^2 - 2), 0) + beta_i * along^2
// along = (p_i.t_i) - (p_j.t_i)
//
// R6: near the HBM write ceiling (~6.2 TB/s pinned across R3-R5). Micro round:
//  - TPB=128 (finer drain granularity, ~6 CTAs/SM -> more store MLP)
//  - sqj computed in-thread (loop-invariant) instead of loaded: 25% less
//    j-side L2 traffic, shallower L1tex queue
//  - keep f32x2 math, alpha-folded chain, packed consts, __stcs

#define MAX_PTS 32768  // B*N max supported (actual: 2*8192 = 16384)

typedef unsigned long long ull;

// j-side SoA:
__device__ float g_px[MAX_PTS];
__device__ float g_py[MAX_PTS];
__device__ float g_pz[MAX_PTS];
// i-side constants, duplicated (v,v) into b64, packed 2 consts per ulonglong2:
// slot 0: (ntx, nty)      slot 1: (ntz, pds)
// slot 2: (alnpx, alnpy)  slot 3: (alnpz, alc1)
// slot 4: (al, be)        slot 5: (alsqi, alsqi)
__device__ ulonglong2 g2c[MAX_PTS * 6];

#define FMA2(d, a, b, c) asm("fma.rn.f32x2 %0, %1, %2, %3;" : "=l"(d) : "l"(a), "l"(b), "l"(c))
#define MUL2(d, a, b)    asm("mul.rn.f32x2 %0, %1, %2;"     : "=l"(d) : "l"(a), "l"(b))
#define PACK2(d, lo, hi) asm("mov.b64 %0, {%1, %2};"        : "=l"(d) : "f"(lo), "f"(hi))
#define UNPACK2(lo, hi, s) asm("mov.b64 {%0, %1}, %2;"      : "=f"(lo), "=f"(hi) : "l"(s))

__device__ __forceinline__ ull dup_f(float v) {
    ull d; PACK2(d, v, v); return d;
}

__global__ void precompute_kernel(const float* __restrict__ points,
                                  const float* __restrict__ pdir,
                                  const float* __restrict__ lin,
                                  int total) {
    int idx = blockIdx.x * blockDim.x + threadIdx.x;
    if (idx >= total) return;
    float px = points[idx * 3 + 0];
    float py = points[idx * 3 + 1];
    float pz = points[idx * 3 + 2];
    float tx = pdir[idx * 3 + 0];
    float ty = pdir[idx * 3 + 1];
    float tz = pdir[idx * 3 + 2];
    float l  = lin[idx];

    g_px[idx] = px; g_py[idx] = py; g_pz[idx] = pz;
    float sq = fmaf(px, px, fmaf(py, py, pz * pz));

    float al = 2.0f * (1.0f + l);
    float be = 0.5f * (1.0f - l);
    float c1 = fmaf(tx, tx, fmaf(ty, ty, tz * tz)) - 2.0f;

    ulonglong2 c;
    c.x = dup_f(-tx);             c.y = dup_f(-ty);
    g2c[idx * 6 + 0] = c;
    c.x = dup_f(-tz);             c.y = dup_f(fmaf(px, tx, fmaf(py, ty, pz * tz)));
    g2c[idx * 6 + 1] = c;
    c.x = dup_f(al * -2.0f * px); c.y = dup_f(al * -2.0f * py);
    g2c[idx * 6 + 2] = c;
    c.x = dup_f(al * -2.0f * pz); c.y = dup_f(al * c1);
    g2c[idx * 6 + 3] = c;
    c.x = dup_f(al);              c.y = dup_f(be);
    g2c[idx * 6 + 4] = c;
    c.x = dup_f(al * sq);         c.y = dup_f(al * sq);
    g2c[idx * 6 + 5] = c;
}

#define TI 16          // i-rows per block
#define TPB 128        // threads per block
// JV=8: each thread owns float4 columns j4a and j4a+TPB -> block covers 2*TPB*4 = 1024 j

// Compute one packed pair (2 j-elements) -> packed result (max folded via alpha>0)
#define PAIR_COMPUTE(pjx, pjy, pjz, sqj, olo, ohi)                     \
    {                                                                  \
        ull u, a2, s, t2;                                              \
        FMA2(u, pjz, ntz, pds);                                        \
        FMA2(u, pjy, nty, u);                                          \
        FMA2(u, pjx, ntx, u);            /* along */                   \
        MUL2(a2, u, u);                  /* along^2 */                 \
        FMA2(s, pjz, alnpz, alsqi);                                    \
        FMA2(s, pjy, alnpy, s);                                        \
        FMA2(s, pjx, alnpx, s);          /* al*(sqi - 2 pj.pi) */      \
        FMA2(s, a2, alc1, s);            /* + al*c1*a2 */              \
        FMA2(s, al, sqj, s);             /* + al*sqj  = al*ns */       \
        MUL2(t2, be, a2);                /* beta*a2 */                 \
        float s0, s1, b0, b1;                                          \
        UNPACK2(s0, s1, s);                                            \
        UNPACK2(b0, b1, t2);                                           \
        olo = fmaxf(s0, 0.0f) + b0;                                    \
        ohi = fmaxf(s1, 0.0f) + b1;                                    \
    }

__global__ __launch_bounds__(TPB, 6) void aniso_main_kernel(float* __restrict__ out, int N) {
    __shared__ ulonglong2 s_c[TI * 6];

    const int b  = blockIdx.z;
    const int i0 = blockIdx.y * TI;
    const int j4a = blockIdx.x * (2 * TPB) + threadIdx.x;  // first float4 column
    const int j4b = j4a + TPB;                             // second float4 column
    const int base = b * N;

    if (threadIdx.x < TI * 6) {
        s_c[threadIdx.x] = g2c[(base + i0) * 6 + threadIdx.x];
    }
    __syncthreads();

    // j-side loads (coalesced float4, L2-resident), packed into b64 pairs once
    const float4 pjxA = reinterpret_cast<const float4*>(g_px + base)[j4a];
    const float4 pjyA = reinterpret_cast<const float4*>(g_py + base)[j4a];
    const float4 pjzA = reinterpret_cast<const float4*>(g_pz + base)[j4a];
    const float4 pjxB = reinterpret_cast<const float4*>(g_px + base)[j4b];
    const float4 pjyB = reinterpret_cast<const float4*>(g_py + base)[j4b];
    const float4 pjzB = reinterpret_cast<const float4*>(g_pz + base)[j4b];

    ull ax01, ax23, ay01, ay23, az01, az23;
    ull bx01, bx23, by01, by23, bz01, bz23;
    PACK2(ax01, pjxA.x, pjxA.y); PACK2(ax23, pjxA.z, pjxA.w);
    PACK2(ay01, pjyA.x, pjyA.y); PACK2(ay23, pjyA.z, pjyA.w);
    PACK2(az01, pjzA.x, pjzA.y); PACK2(az23, pjzA.z, pjzA.w);
    PACK2(bx01, pjxB.x, pjxB.y); PACK2(bx23, pjxB.z, pjxB.w);
    PACK2(by01, pjyB.x, pjyB.y); PACK2(by23, pjyB.z, pjyB.w);
    PACK2(bz01, pjzB.x, pjzB.y); PACK2(bz23, pjzB.z, pjzB.w);

    // sqj computed in-registers (loop-invariant), packed f32x2
    ull as01, as23, bs01, bs23;
    {
        ull t;
        MUL2(t, az01, az01); FMA2(t, ay01, ay01, t); FMA2(as01, ax01, ax01, t);
        MUL2(t, az23, az23); FMA2(t, ay23, ay23, t); FMA2(as23, ax23, ax23, t);
        MUL2(t, bz01, bz01); FMA2(t, by01, by01, t); FMA2(bs01, bx01, bx01, t);
        MUL2(t, bz23, bz23); FMA2(t, by23, by23, t); FMA2(bs23, bx23, bx23, t);
    }

    float* orowA = out + ((size_t)b * N + i0) * N + j4a * 4;
    float* orowB = out + ((size_t)b * N + i0) * N + j4b * 4;

    #pragma unroll
    for (int ii = 0; ii < TI; ii++) {
        const ulonglong2 c0 = s_c[ii * 6 + 0];
        const ulonglong2 c1v = s_c[ii * 6 + 1];
        const ulonglong2 c2 = s_c[ii * 6 + 2];
        const ulonglong2 c3 = s_c[ii * 6 + 3];
        const ulonglong2 c4 = s_c[ii * 6 + 4];
        const ulonglong2 c5 = s_c[ii * 6 + 5];
        const ull ntx = c0.x, nty = c0.y, ntz = c1v.x, pds = c1v.y;
        const ull alnpx = c2.x, alnpy = c2.y, alnpz = c3.x, alc1 = c3.y;
        const ull al = c4.x, be = c4.y, alsqi = c5.x;

        float4 oA, oB;
        PAIR_COMPUTE(ax01, ay01, az01, as01, oA.x, oA.y);
        PAIR_COMPUTE(ax23, ay23, az23, as23, oA.z, oA.w);
        PAIR_COMPUTE(bx01, by01, bz01, bs01, oB.x, oB.y);
        PAIR_COMPUTE(bx23, by23, bz23, bs23, oB.z, oB.w);

        __stcs(reinterpret_cast<float4*>(orowA), oA);
        __stcs(reinterpret_cast<float4*>(orowB), oB);
        orowA += N;
        orowB += N;
    }
}

extern "C" void kernel_launch(void* const* d_in, const int* in_sizes, int n_in,
                              void* d_out, int out_size) {
    const float* points = (const float*)d_in[0];
    const float* pdir   = (const float*)d_in[1];
    const float* lin    = (const float*)d_in[2];
    float* out = (float*)d_out;

    const int total = in_sizes[0] / 3;                 // B*N points
    const int N = (int)((long long)out_size / total);  // out = B*N*N
    const int B = total / N;

    precompute_kernel<<<(total + 255) / 256, 256>>>(points, pdir, lin, total);

    // block covers 2*TPB*4 = 1024 j columns
    dim3 grid((N + 2 * TPB * 4 - 1) / (2 * TPB * 4), (N + TI - 1) / TI, B);
    aniso_main_kernel<<<grid, TPB>>>(out, N);
}

// round 8
// speedup vs baseline: 1.0095x; 1.0095x over previous
#include <cuda_runtime.h>
#include <cuda_bf16.h>

// AnisotropicDistance:
// out[b,i,j] = alpha_i * max(||p_i-p_j||^2 + along^2*(||t_i||^2 - 2), 0) + beta_i * along^2
// along = (p_i.t_i) - (p_j.t_i)
//
// R7 (final config): best-measured R4 shape (TI=16, TPB=256, JV=4,
// launch_bounds(256,4), packed f32x2 math, alpha-folded chain, packed smem
// constants, __stcs streaming stores) + in-register sqj (one fewer j-side
// LDG.128 per thread). DRAM write stream is the binding resource (~6.2 TB/s
// = HBM3e pure-write ceiling); kernel is at that floor.

#define MAX_PTS 32768  // B*N max supported (actual: 2*8192 = 16384)

typedef unsigned long long ull;

// j-side SoA:
__device__ float g_px[MAX_PTS];
__device__ float g_py[MAX_PTS];
__device__ float g_pz[MAX_PTS];
// i-side constants, duplicated (v,v) into b64, packed 2 consts per ulonglong2:
// slot 0: (ntx, nty)      slot 1: (ntz, pds)
// slot 2: (alnpx, alnpy)  slot 3: (alnpz, alc1)
// slot 4: (al, be)        slot 5: (alsqi, alsqi)
__device__ ulonglong2 g2c[MAX_PTS * 6];

#define FMA2(d, a, b, c) asm("fma.rn.f32x2 %0, %1, %2, %3;" : "=l"(d) : "l"(a), "l"(b), "l"(c))
#define MUL2(d, a, b)    asm("mul.rn.f32x2 %0, %1, %2;"     : "=l"(d) : "l"(a), "l"(b))
#define PACK2(d, lo, hi) asm("mov.b64 %0, {%1, %2};"        : "=l"(d) : "f"(lo), "f"(hi))
#define UNPACK2(lo, hi, s) asm("mov.b64 {%0, %1}, %2;"      : "=f"(lo), "=f"(hi) : "l"(s))

__device__ __forceinline__ ull dup_f(float v) {
    ull d; PACK2(d, v, v); return d;
}

__global__ void precompute_kernel(const float* __restrict__ points,
                                  const float* __restrict__ pdir,
                                  const float* __restrict__ lin,
                                  int total) {
    int idx = blockIdx.x * blockDim.x + threadIdx.x;
    if (idx >= total) return;
    float px = points[idx * 3 + 0];
    float py = points[idx * 3 + 1];
    float pz = points[idx * 3 + 2];
    float tx = pdir[idx * 3 + 0];
    float ty = pdir[idx * 3 + 1];
    float tz = pdir[idx * 3 + 2];
    float l  = lin[idx];

    g_px[idx] = px; g_py[idx] = py; g_pz[idx] = pz;
    float sq = fmaf(px, px, fmaf(py, py, pz * pz));

    float al = 2.0f * (1.0f + l);
    float be = 0.5f * (1.0f - l);
    float c1 = fmaf(tx, tx, fmaf(ty, ty, tz * tz)) - 2.0f;

    ulonglong2 c;
    c.x = dup_f(-tx);             c.y = dup_f(-ty);
    g2c[idx * 6 + 0] = c;
    c.x = dup_f(-tz);             c.y = dup_f(fmaf(px, tx, fmaf(py, ty, pz * tz)));
    g2c[idx * 6 + 1] = c;
    c.x = dup_f(al * -2.0f * px); c.y = dup_f(al * -2.0f * py);
    g2c[idx * 6 + 2] = c;
    c.x = dup_f(al * -2.0f * pz); c.y = dup_f(al * c1);
    g2c[idx * 6 + 3] = c;
    c.x = dup_f(al);              c.y = dup_f(be);
    g2c[idx * 6 + 4] = c;
    c.x = dup_f(al * sq);         c.y = dup_f(al * sq);
    g2c[idx * 6 + 5] = c;
}

#define TI 16          // i-rows per block
#define TPB 256        // threads per block
#define JV 4           // j per thread (one float4 store) -> block covers 1024 j

// Compute one packed pair (2 j-elements) -> result (max folded via alpha>0)
#define PAIR_COMPUTE(pjx, pjy, pjz, sqj, olo, ohi)                     \
    {                                                                  \
        ull u, a2, s, t2;                                              \
        FMA2(u, pjz, ntz, pds);                                        \
        FMA2(u, pjy, nty, u);                                          \
        FMA2(u, pjx, ntx, u);            /* along */                   \
        MUL2(a2, u, u);                  /* along^2 */                 \
        FMA2(s, pjz, alnpz, alsqi);                                    \
        FMA2(s, pjy, alnpy, s);                                        \
        FMA2(s, pjx, alnpx, s);          /* al*(sqi - 2 pj.pi) */      \
        FMA2(s, a2, alc1, s);            /* + al*c1*a2 */              \
        FMA2(s, al, sqj, s);             /* + al*sqj = al*ns */        \
        MUL2(t2, be, a2);                /* beta*a2 */                 \
        float s0, s1, b0, b1;                                          \
        UNPACK2(s0, s1, s);                                            \
        UNPACK2(b0, b1, t2);                                           \
        olo = fmaxf(s0, 0.0f) + b0;                                    \
        ohi = fmaxf(s1, 0.0f) + b1;                                    \
    }

__global__ __launch_bounds__(TPB, 4) void aniso_main_kernel(float* __restrict__ out, int N) {
    __shared__ ulonglong2 s_c[TI * 6];

    const int b  = blockIdx.z;
    const int i0 = blockIdx.y * TI;
    const int j4 = blockIdx.x * TPB + threadIdx.x;   // float4 index in j
    const int j  = j4 * JV;
    const int base = b * N;

    if (threadIdx.x < TI * 6) {
        s_c[threadIdx.x] = g2c[(base + i0) * 6 + threadIdx.x];
    }
    __syncthreads();

    if (j >= N) return;

    // j-side loads (coalesced float4, L2-resident), packed into b64 pairs once
    const float4 pjx = reinterpret_cast<const float4*>(g_px + base)[j4];
    const float4 pjy = reinterpret_cast<const float4*>(g_py + base)[j4];
    const float4 pjz = reinterpret_cast<const float4*>(g_pz + base)[j4];

    ull ax01, ax23, ay01, ay23, az01, az23;
    PACK2(ax01, pjx.x, pjx.y); PACK2(ax23, pjx.z, pjx.w);
    PACK2(ay01, pjy.x, pjy.y); PACK2(ay23, pjy.z, pjy.w);
    PACK2(az01, pjz.x, pjz.y); PACK2(az23, pjz.z, pjz.w);

    // sqj computed in-registers (loop-invariant), packed f32x2
    ull as01, as23;
    {
        ull t;
        MUL2(t, az01, az01); FMA2(t, ay01, ay01, t); FMA2(as01, ax01, ax01, t);
        MUL2(t, az23, az23); FMA2(t, ay23, ay23, t); FMA2(as23, ax23, ax23, t);
    }

    float* orow = out + ((size_t)b * N + i0) * N + j;

    #pragma unroll
    for (int ii = 0; ii < TI; ii++) {
        const ulonglong2 c0 = s_c[ii * 6 + 0];
        const ulonglong2 c1v = s_c[ii * 6 + 1];
        const ulonglong2 c2 = s_c[ii * 6 + 2];
        const ulonglong2 c3 = s_c[ii * 6 + 3];
        const ulonglong2 c4 = s_c[ii * 6 + 4];
        const ulonglong2 c5 = s_c[ii * 6 + 5];
        const ull ntx = c0.x, nty = c0.y, ntz = c1v.x, pds = c1v.y;
        const ull alnpx = c2.x, alnpy = c2.y, alnpz = c3.x, alc1 = c3.y;
        const ull al = c4.x, be = c4.y, alsqi = c5.x;

        float4 o;
        PAIR_COMPUTE(ax01, ay01, az01, as01, o.x, o.y);
        PAIR_COMPUTE(ax23, ay23, az23, as23, o.z, o.w);

        __stcs(reinterpret_cast<float4*>(orow), o);
        orow += N;
    }
}

extern "C" void kernel_launch(void* const* d_in, const int* in_sizes, int n_in,
                              void* d_out, int out_size) {
    const float* points = (const float*)d_in[0];
    const float* pdir   = (const float*)d_in[1];
    const float* lin    = (const float*)d_in[2];
    float* out = (float*)d_out;

    const int total = in_sizes[0] / 3;                 // B*N points
    const int N = (int)((long long)out_size / total);  // out = B*N*N
    const int B = total / N;

    precompute_kernel<<<(total + 255) / 256, 256>>>(points, pdir, lin, total);

    dim3 grid((N + TPB * JV - 1) / (TPB * JV), (N + TI - 1) / TI, B);
    aniso_main_kernel<<<grid, TPB>>>(out, N);
}